// round 10
// baseline (speedup 1.0000x reference)
#include <cuda_runtime.h>
#include <cuda_fp16.h>

#define BATCH 32768
#define NF 64
#define NB 33          // bounds per feature
#define NP 32          // pieces = NB-1
#define E  64          // embedding per feature

// Packed table, 256B per (f,j): 16 float4 chunks. Chunk q (outputs 4q..4q+3)
// holds halves (c0,c1,w0,w1,c2,c3,w2,w3):
//   .x=(c0,c1) .y=(w0,w1) .z=(c2,c3) .w=(w2,w3)  -> 2x HFMA2 per chunk.
// c[f][j][e] = b[f][e] + sum_{i<j} W[f][i][e];  w[f][j][e] = W[f][j][e] (0 at j=32)
// 32B-aligned so chunk PAIRS can be read with 256-bit loads.
__device__ __align__(32) float4 g_P4[NF * NB * 16];   // 540 KB

// Transposed bounds for coalesced search: bT[k][f]
__device__ float g_bT[NB * NF];

// ---------------------------------------------------------------------------
// Prep: one thread per (f, e); 2B half stores, no races. Also transpose bounds.
// ---------------------------------------------------------------------------
__global__ void pwl_prep(const float* __restrict__ W,
                         const float* __restrict__ bias,
                         const float* __restrict__ bounds) {
    int idx = blockIdx.x * blockDim.x + threadIdx.x;
    if (idx < NB * NF) {
        int k = idx >> 6;
        int f = idx & 63;
        g_bT[idx] = bounds[f * NB + k];
    }
    if (idx >= NF * E) return;
    int f = idx >> 6;
    int e = idx & 63;
    int l = e & 3;
    int hc = ((e >> 2) << 3) + (l & 1) + ((l & 2) << 1);
    __half* gp = reinterpret_cast<__half*>(g_P4);
    float c = bias[f * E + e];
#pragma unroll
    for (int j = 0; j < NP; j++) {
        float w = W[(f * NP + j) * E + e];
        __half* row = gp + ((f * NB + j) << 7);
        row[hc]     = __float2half_rn(c);
        row[hc + 2] = __float2half_rn(w);
        c += w;
    }
    __half* row = gp + ((f * NB + NP) << 7);
    row[hc]     = __float2half_rn(c);
    row[hc + 2] = __half(0.0f);
}

__device__ __forceinline__ __half2 f_as_h2(float v) {
    unsigned u = __float_as_uint(v);
    return *reinterpret_cast<__half2*>(&u);
}

// ---------------------------------------------------------------------------
// Main: one block per batch row, 128 threads, 4 v8 (256-bit) slots per thread.
//   Phase 1: threads 0..63 -> (float4 table base, frac as half2).
//   Phase 2: per slot: LDG.256 (table, L1/L2-hot) -> 4x HFMA2/HMAX2 ->
//            STG.256 streaming. Interleaved per slot (measured optimum).
// ---------------------------------------------------------------------------
__global__ __launch_bounds__(128, 16)
void pwl_main(const float* __restrict__ X,
              float* __restrict__ out) {
    __shared__ int      s_base[NF];
    __shared__ unsigned s_fr[NF];

    int b = blockIdx.x;
    int t = threadIdx.x;

    if (t < NF) {
        float x = X[b * NF + t];
        int j = 0;
#pragma unroll
        for (int k = 1; k <= NP; k++) j += (x >= g_bT[k * NF + t]) ? 1 : 0;
        float frac = 0.0f;
        if (j < NP) {
            float lo = g_bT[j * NF + t];
            float hi = g_bT[(j + 1) * NF + t];
            frac = fminf(fmaxf((x - lo) / (hi - lo), 0.0f), 1.0f);
        }
        s_base[t] = (t * NB + j) << 4;      // float4 index of P[f][j] chunk 0
        __half2 h2 = __float2half2_rn(frac);
        s_fr[t] = *reinterpret_cast<unsigned*>(&h2);
    }
    __syncthreads();

    float* orow = out + (size_t)b * (NF * E);
    const __half2 zero2 = __float2half2_rn(0.0f);

#pragma unroll
    for (int rep = 0; rep < 4; rep++) {
        int i8 = t + rep * 128;             // 0..511 float8 slots
        int f  = i8 >> 3;                   // 8 float8 per feature
        int e8 = i8 & 7;
        unsigned fru = s_fr[f];
        __half2 f2 = *reinterpret_cast<__half2*>(&fru);

        const float* tp = reinterpret_cast<const float*>(g_P4 + s_base[f] + 2 * e8);
        float p0, p1, p2, p3, p4, p5, p6, p7;
        asm volatile("ld.global.v8.f32 {%0,%1,%2,%3,%4,%5,%6,%7}, [%8];"
                     : "=f"(p0), "=f"(p1), "=f"(p2), "=f"(p3),
                       "=f"(p4), "=f"(p5), "=f"(p6), "=f"(p7)
                     : "l"(tp));

        __half2 rA0 = __hmax2(__hfma2(f2, f_as_h2(p1), f_as_h2(p0)), zero2);
        __half2 rA1 = __hmax2(__hfma2(f2, f_as_h2(p3), f_as_h2(p2)), zero2);
        __half2 rB0 = __hmax2(__hfma2(f2, f_as_h2(p5), f_as_h2(p4)), zero2);
        __half2 rB1 = __hmax2(__hfma2(f2, f_as_h2(p7), f_as_h2(p6)), zero2);
        float2 a0 = __half22float2(rA0);
        float2 a1 = __half22float2(rA1);
        float2 b0 = __half22float2(rB0);
        float2 b1 = __half22float2(rB1);

        float* op = orow + i8 * 8;
        asm volatile("st.global.cs.v8.f32 [%0], {%1,%2,%3,%4,%5,%6,%7,%8};"
                     :: "l"(op),
                        "f"(a0.x), "f"(a0.y), "f"(a1.x), "f"(a1.y),
                        "f"(b0.x), "f"(b0.y), "f"(b1.x), "f"(b1.y)
                     : "memory");
    }
}

extern "C" void kernel_launch(void* const* d_in, const int* in_sizes, int n_in,
                              void* d_out, int out_size) {
    const float* X      = (const float*)d_in[0];   // (32768, 64)
    const float* bounds = (const float*)d_in[1];   // (64, 33)
    const float* W      = (const float*)d_in[2];   // (64, 32, 64)
    const float* bias   = (const float*)d_in[3];   // (64, 64)
    float* out = (float*)d_out;                    // (32768, 4096)

    pwl_prep<<<(NF * E + 255) / 256, 256>>>(W, bias, bounds);
    pwl_main<<<BATCH, 128>>>(X, out);
}

// round 11
// speedup vs baseline: 1.0687x; 1.0687x over previous
#include <cuda_runtime.h>
#include <cuda_fp16.h>

#define BATCH 32768
#define NF 64
#define NB 33          // bounds per feature
#define NP 32          // pieces = NB-1
#define E  64          // embedding per feature

// Packed table, 256B per (f,j): 16 float4 chunks. Chunk q (outputs 4q..4q+3)
// holds halves (c0,c1,w0,w1,c2,c3,w2,w3):
//   .x=(c0,c1) .y=(w0,w1) .z=(c2,c3) .w=(w2,w3)  -> 2x HFMA2 per chunk.
// c[f][j][e] = b[f][e] + sum_{i<j} W[f][i][e];  w[f][j][e] = W[f][j][e] (0 at j=32)
__device__ float4 g_P4[NF * NB * 16];            // 540 KB

// Transposed bounds for coalesced search: bT[k][f]
__device__ float g_bT[NB * NF];

// ---------------------------------------------------------------------------
// Prep: one thread per (f, chunk q). Each thread walks j=0..32 keeping 4 fp32
// prefix accumulators and writes ONE packed 16B float4 per (f,j,q) — full-width
// stores, no sub-word write-combining.
// ---------------------------------------------------------------------------
__global__ void pwl_prep(const float* __restrict__ W,
                         const float* __restrict__ bias,
                         const float* __restrict__ bounds) {
    int idx = blockIdx.x * blockDim.x + threadIdx.x;     // 0..1023 (+ transpose part)
    if (idx < NB * NF) {
        int k = idx >> 6;
        int f = idx & 63;
        g_bT[idx] = bounds[f * NB + k];
    }
    if (idx >= NF * 16) return;
    int f = idx >> 4;       // feature
    int q = idx & 15;       // chunk (covers e = 4q..4q+3)
    int e = q << 2;

    const float4* b4 = reinterpret_cast<const float4*>(bias + f * E + e);
    float4 c = *b4;

    #pragma unroll 1
    for (int j = 0; j < NP; j++) {
        float4 w = *reinterpret_cast<const float4*>(W + ((f * NP + j) * E + e));
        float4 chunk;
        __half2 h;
        h = __floats2half2_rn(c.x, c.y); chunk.x = *reinterpret_cast<float*>(&h);
        h = __floats2half2_rn(w.x, w.y); chunk.y = *reinterpret_cast<float*>(&h);
        h = __floats2half2_rn(c.z, c.w); chunk.z = *reinterpret_cast<float*>(&h);
        h = __floats2half2_rn(w.z, w.w); chunk.w = *reinterpret_cast<float*>(&h);
        g_P4[((f * NB + j) << 4) + q] = chunk;
        c.x += w.x; c.y += w.y; c.z += w.z; c.w += w.w;
    }
    {   // j = 32 terminal piece: slope 0
        float4 chunk;
        __half2 h;
        h = __floats2half2_rn(c.x, c.y); chunk.x = *reinterpret_cast<float*>(&h);
        h = __floats2half2_rn(0.f, 0.f); chunk.y = *reinterpret_cast<float*>(&h);
        h = __floats2half2_rn(c.z, c.w); chunk.z = *reinterpret_cast<float*>(&h);
        chunk.w = chunk.y;
        g_P4[((f * NB + NP) << 4) + q] = chunk;
    }
}

// ---------------------------------------------------------------------------
// Main (round-4/9 measured winner — DO NOT PERTURB):
// one block per batch row, 256 threads, 4 float4 slots per thread.
//   Phase 1: threads 0..63 -> (float4 table base, frac as half2).
//   Phase 2: per slot: LDG.128 (L1/L2-resident table) -> 2xHFMA2/HMAX2 ->
//            4 CVT -> STG.128 streaming. Interleaved per slot.
// ---------------------------------------------------------------------------
__global__ __launch_bounds__(256, 8)
void pwl_main(const float* __restrict__ X,
              float* __restrict__ out) {
    __shared__ int      s_base[NF];
    __shared__ unsigned s_fr[NF];

    int b = blockIdx.x;
    int t = threadIdx.x;

    if (t < NF) {
        float x = X[b * NF + t];
        int j = 0;
#pragma unroll
        for (int k = 1; k <= NP; k++) j += (x >= g_bT[k * NF + t]) ? 1 : 0;
        float frac = 0.0f;
        if (j < NP) {
            float lo = g_bT[j * NF + t];
            float hi = g_bT[(j + 1) * NF + t];
            frac = fminf(fmaxf((x - lo) / (hi - lo), 0.0f), 1.0f);
        }
        s_base[t] = (t * NB + j) << 4;      // float4 index of P[f][j] chunk 0
        __half2 h2 = __float2half2_rn(frac);
        s_fr[t] = *reinterpret_cast<unsigned*>(&h2);
    }
    __syncthreads();

    float4* out4 = reinterpret_cast<float4*>(out + (size_t)b * (NF * E));
    const __half2 zero2 = __float2half2_rn(0.0f);

#pragma unroll
    for (int rep = 0; rep < 4; rep++) {
        int i  = t + rep * 256;             // 0..1023 float4 slots
        int f  = i >> 4;                    // 16 float4 per feature
        int e4 = i & 15;
        int base     = s_base[f];
        unsigned fru = s_fr[f];
        __half2 f2 = *reinterpret_cast<__half2*>(&fru);

        float4 p = g_P4[base + e4];
        __half2 c01 = *reinterpret_cast<__half2*>(&p.x);
        __half2 w01 = *reinterpret_cast<__half2*>(&p.y);
        __half2 c23 = *reinterpret_cast<__half2*>(&p.z);
        __half2 w23 = *reinterpret_cast<__half2*>(&p.w);

        __half2 r01 = __hmax2(__hfma2(f2, w01, c01), zero2);
        __half2 r23 = __hmax2(__hfma2(f2, w23, c23), zero2);
        float2 o01 = __half22float2(r01);
        float2 o23 = __half22float2(r23);

        __stcs(out4 + i, make_float4(o01.x, o01.y, o23.x, o23.y));
    }
}

extern "C" void kernel_launch(void* const* d_in, const int* in_sizes, int n_in,
                              void* d_out, int out_size) {
    const float* X      = (const float*)d_in[0];   // (32768, 64)
    const float* bounds = (const float*)d_in[1];   // (64, 33)
    const float* W      = (const float*)d_in[2];   // (64, 32, 64)
    const float* bias   = (const float*)d_in[3];   // (64, 64)
    float* out = (float*)d_out;                    // (32768, 4096)

    // prep needs max(NB*NF, NF*16) = 2112 threads total
    pwl_prep<<<9, 256>>>(W, bias, bounds);
    pwl_main<<<BATCH, 256>>>(X, out);
}

// round 12
// speedup vs baseline: 1.1181x; 1.0463x over previous
#include <cuda_runtime.h>
#include <cuda_fp16.h>

#define BATCH 32768
#define NF 64
#define NB 33          // bounds per feature
#define NP 32          // pieces = NB-1
#define E  64          // embedding per feature

// Packed table, 256B per (f,j): 16 float4 chunks. Chunk q (outputs 4q..4q+3)
// holds halves (c0,c1,w0,w1,c2,c3,w2,w3):
//   .x=(c0,c1) .y=(w0,w1) .z=(c2,c3) .w=(w2,w3)  -> 2x HFMA2 per chunk.
// c[f][j][e] = b[f][e] + sum_{i<j} W[f][i][e];  w[f][j][e] = W[f][j][e] (0 at j=32)
__device__ float4 g_P4[NF * NB * 16];            // 540 KB

// Transposed bounds for coalesced search: bT[k][f]
__device__ float g_bT[NB * NF];

// ---------------------------------------------------------------------------
// Prep: one thread per (f, e); fully unrolled so the 32 W loads pipeline
// (load-latency bound, not store bound). 2B half stores, no races.
// Also transposes bounds.
// ---------------------------------------------------------------------------
__global__ void pwl_prep(const float* __restrict__ W,
                         const float* __restrict__ bias,
                         const float* __restrict__ bounds) {
    int idx = blockIdx.x * blockDim.x + threadIdx.x;
    if (idx < NB * NF) {
        int k = idx >> 6;
        int f = idx & 63;
        g_bT[idx] = bounds[f * NB + k];
    }
    if (idx >= NF * E) return;
    int f = idx >> 6;
    int e = idx & 63;
    int l = e & 3;
    int hc = ((e >> 2) << 3) + (l & 1) + ((l & 2) << 1);
    __half* gp = reinterpret_cast<__half*>(g_P4);
    float c = bias[f * E + e];
#pragma unroll
    for (int j = 0; j < NP; j++) {
        float w = W[(f * NP + j) * E + e];
        __half* row = gp + ((f * NB + j) << 7);
        row[hc]     = __float2half_rn(c);
        row[hc + 2] = __float2half_rn(w);
        c += w;
    }
    __half* row = gp + ((f * NB + NP) << 7);
    row[hc]     = __float2half_rn(c);
    row[hc + 2] = __half(0.0f);
}

// ---------------------------------------------------------------------------
// Main (measured winner, rounds 4 & 9): one block per batch row, 256 threads,
// 4 float4 slots per thread.
//   Phase 1: threads 0..63 -> (float4 table base, frac as half2).
//   Phase 2: per slot: LDG.128 (L1/L2-resident table) -> 2xHFMA2/HMAX2 ->
//            4 CVT -> STG.128 streaming. Interleaved per slot.
// ---------------------------------------------------------------------------
__global__ __launch_bounds__(256, 8)
void pwl_main(const float* __restrict__ X,
              float* __restrict__ out) {
    __shared__ int      s_base[NF];
    __shared__ unsigned s_fr[NF];

    int b = blockIdx.x;
    int t = threadIdx.x;

    if (t < NF) {
        float x = X[b * NF + t];
        int j = 0;
#pragma unroll
        for (int k = 1; k <= NP; k++) j += (x >= g_bT[k * NF + t]) ? 1 : 0;
        float frac = 0.0f;
        if (j < NP) {
            float lo = g_bT[j * NF + t];
            float hi = g_bT[(j + 1) * NF + t];
            frac = fminf(fmaxf((x - lo) / (hi - lo), 0.0f), 1.0f);
        }
        s_base[t] = (t * NB + j) << 4;      // float4 index of P[f][j] chunk 0
        __half2 h2 = __float2half2_rn(frac);
        s_fr[t] = *reinterpret_cast<unsigned*>(&h2);
    }
    __syncthreads();

    float4* out4 = reinterpret_cast<float4*>(out + (size_t)b * (NF * E));
    const __half2 zero2 = __float2half2_rn(0.0f);

#pragma unroll
    for (int rep = 0; rep < 4; rep++) {
        int i  = t + rep * 256;             // 0..1023 float4 slots
        int f  = i >> 4;                    // 16 float4 per feature
        int e4 = i & 15;
        int base     = s_base[f];
        unsigned fru = s_fr[f];
        __half2 f2 = *reinterpret_cast<__half2*>(&fru);

        float4 p = g_P4[base + e4];
        __half2 c01 = *reinterpret_cast<__half2*>(&p.x);
        __half2 w01 = *reinterpret_cast<__half2*>(&p.y);
        __half2 c23 = *reinterpret_cast<__half2*>(&p.z);
        __half2 w23 = *reinterpret_cast<__half2*>(&p.w);

        __half2 r01 = __hmax2(__hfma2(f2, w01, c01), zero2);
        __half2 r23 = __hmax2(__hfma2(f2, w23, c23), zero2);
        float2 o01 = __half22float2(r01);
        float2 o23 = __half22float2(r23);

        __stcs(out4 + i, make_float4(o01.x, o01.y, o23.x, o23.y));
    }
}

extern "C" void kernel_launch(void* const* d_in, const int* in_sizes, int n_in,
                              void* d_out, int out_size) {
    const float* X      = (const float*)d_in[0];   // (32768, 64)
    const float* bounds = (const float*)d_in[1];   // (64, 33)
    const float* W      = (const float*)d_in[2];   // (64, 32, 64)
    const float* bias   = (const float*)d_in[3];   // (64, 64)
    float* out = (float*)d_out;                    // (32768, 4096)

    pwl_prep<<<(NF * E + 255) / 256, 256>>>(W, bias, bounds);
    pwl_main<<<BATCH, 256>>>(X, out);
}

// round 13
// speedup vs baseline: 1.1195x; 1.0012x over previous
#include <cuda_runtime.h>
#include <cuda_fp16.h>

#define BATCH 32768
#define NF 64
#define NB 33          // bounds per feature
#define NP 32          // pieces = NB-1
#define E  64          // embedding per feature

// Packed table, 256B per (f,j): 16 float4 chunks. Chunk q (outputs 4q..4q+3)
// holds halves (c0,c1,w0,w1,c2,c3,w2,w3):
//   .x=(c0,c1) .y=(w0,w1) .z=(c2,c3) .w=(w2,w3)  -> 2x HFMA2 per chunk.
// c[f][j][e] = b[f][e] + sum_{i<j} W[f][i][e];  w[f][j][e] = W[f][j][e] (0 at j=32)
__device__ float4 g_P4[NF * NB * 16];            // 540 KB

// Transposed bounds for coalesced search: bT[k][f]
__device__ float g_bT[NB * NF];

// ---------------------------------------------------------------------------
// Prep: one thread per (f, e); fully unrolled so the 32 W loads pipeline
// (load-latency bound, not store bound). 2B half stores, no races.
// Also transposes bounds.
// ---------------------------------------------------------------------------
__global__ void pwl_prep(const float* __restrict__ W,
                         const float* __restrict__ bias,
                         const float* __restrict__ bounds) {
    int idx = blockIdx.x * blockDim.x + threadIdx.x;
    if (idx < NB * NF) {
        int k = idx >> 6;
        int f = idx & 63;
        g_bT[idx] = bounds[f * NB + k];
    }
    if (idx >= NF * E) return;
    int f = idx >> 6;
    int e = idx & 63;
    int l = e & 3;
    int hc = ((e >> 2) << 3) + (l & 1) + ((l & 2) << 1);
    __half* gp = reinterpret_cast<__half*>(g_P4);
    float c = bias[f * E + e];
#pragma unroll
    for (int j = 0; j < NP; j++) {
        float w = W[(f * NP + j) * E + e];
        __half* row = gp + ((f * NB + j) << 7);
        row[hc]     = __float2half_rn(c);
        row[hc + 2] = __float2half_rn(w);
        c += w;
    }
    __half* row = gp + ((f * NB + NP) << 7);
    row[hc]     = __float2half_rn(c);
    row[hc + 2] = __half(0.0f);
}

// ---------------------------------------------------------------------------
// Main (measured winner, rounds 4/9/12): one block per batch row, 256 threads,
// 4 float4 slots per thread.
//   Phase 1: threads 0..63 -> (float4 table base, frac as half2).
//   Phase 2: per slot: LDG.128 (L1/L2-resident table) -> 2xHFMA2/HMAX2 ->
//            4 CVT -> STG.128 streaming. Interleaved per slot.
// ---------------------------------------------------------------------------
__global__ __launch_bounds__(256, 8)
void pwl_main(const float* __restrict__ X,
              float* __restrict__ out) {
    __shared__ int      s_base[NF];
    __shared__ unsigned s_fr[NF];

    int b = blockIdx.x;
    int t = threadIdx.x;

    if (t < NF) {
        float x = X[b * NF + t];
        int j = 0;
#pragma unroll
        for (int k = 1; k <= NP; k++) j += (x >= g_bT[k * NF + t]) ? 1 : 0;
        float frac = 0.0f;
        if (j < NP) {
            float lo = g_bT[j * NF + t];
            float hi = g_bT[(j + 1) * NF + t];
            frac = fminf(fmaxf((x - lo) / (hi - lo), 0.0f), 1.0f);
        }
        s_base[t] = (t * NB + j) << 4;      // float4 index of P[f][j] chunk 0
        __half2 h2 = __float2half2_rn(frac);
        s_fr[t] = *reinterpret_cast<unsigned*>(&h2);
    }
    __syncthreads();

    float4* out4 = reinterpret_cast<float4*>(out + (size_t)b * (NF * E));
    const __half2 zero2 = __float2half2_rn(0.0f);

#pragma unroll
    for (int rep = 0; rep < 4; rep++) {
        int i  = t + rep * 256;             // 0..1023 float4 slots
        int f  = i >> 4;                    // 16 float4 per feature
        int e4 = i & 15;
        int base     = s_base[f];
        unsigned fru = s_fr[f];
        __half2 f2 = *reinterpret_cast<__half2*>(&fru);

        float4 p = g_P4[base + e4];
        __half2 c01 = *reinterpret_cast<__half2*>(&p.x);
        __half2 w01 = *reinterpret_cast<__half2*>(&p.y);
        __half2 c23 = *reinterpret_cast<__half2*>(&p.z);
        __half2 w23 = *reinterpret_cast<__half2*>(&p.w);

        __half2 r01 = __hmax2(__hfma2(f2, w01, c01), zero2);
        __half2 r23 = __hmax2(__hfma2(f2, w23, c23), zero2);
        float2 o01 = __half22float2(r01);
        float2 o23 = __half22float2(r23);

        __stcs(out4 + i, make_float4(o01.x, o01.y, o23.x, o23.y));
    }
}

extern "C" void kernel_launch(void* const* d_in, const int* in_sizes, int n_in,
                              void* d_out, int out_size) {
    const float* X      = (const float*)d_in[0];   // (32768, 64)
    const float* bounds = (const float*)d_in[1];   // (64, 33)
    const float* W      = (const float*)d_in[2];   // (64, 32, 64)
    const float* bias   = (const float*)d_in[3];   // (64, 64)
    float* out = (float*)d_out;                    // (32768, 4096)

    pwl_prep<<<(NF * E + 255) / 256, 256>>>(W, bias, bounds);
    pwl_main<<<BATCH, 256>>>(X, out);
}

// round 14
// speedup vs baseline: 1.1254x; 1.0053x over previous
#include <cuda_runtime.h>
#include <cuda_fp16.h>

#define BATCH 32768
#define NF 64
#define NB 33          // bounds per feature
#define NP 32          // pieces = NB-1
#define E  64          // embedding per feature

// Packed table, 256B per (f,j): 16 float4 chunks. Chunk q (outputs 4q..4q+3)
// holds halves (c0,c1,w0,w1,c2,c3,w2,w3):
//   .x=(c0,c1) .y=(w0,w1) .z=(c2,c3) .w=(w2,w3)  -> 2x HFMA2 per chunk.
// c[f][j][e] = b[f][e] + sum_{i<j} W[f][i][e];  w[f][j][e] = W[f][j][e] (0 at j=32)
__device__ float4 g_P4[NF * NB * 16];            // 540 KB

// Transposed bounds for coalesced search: bT[k][f]
__device__ float g_bT[NB * NF];

// ---------------------------------------------------------------------------
// Prep: one thread per (f, e); fully unrolled so the 32 W loads pipeline
// (load-latency bound, not store bound). 2B half stores, no races.
// Also transposes bounds.
// ---------------------------------------------------------------------------
__global__ void pwl_prep(const float* __restrict__ W,
                         const float* __restrict__ bias,
                         const float* __restrict__ bounds) {
    int idx = blockIdx.x * blockDim.x + threadIdx.x;
    if (idx < NB * NF) {
        int k = idx >> 6;
        int f = idx & 63;
        g_bT[idx] = bounds[f * NB + k];
    }
    if (idx >= NF * E) return;
    int f = idx >> 6;
    int e = idx & 63;
    int l = e & 3;
    int hc = ((e >> 2) << 3) + (l & 1) + ((l & 2) << 1);
    __half* gp = reinterpret_cast<__half*>(g_P4);
    float c = bias[f * E + e];
#pragma unroll
    for (int j = 0; j < NP; j++) {
        float w = W[(f * NP + j) * E + e];
        __half* row = gp + ((f * NB + j) << 7);
        row[hc]     = __float2half_rn(c);
        row[hc + 2] = __float2half_rn(w);
        c += w;
    }
    __half* row = gp + ((f * NB + NP) << 7);
    row[hc]     = __float2half_rn(c);
    row[hc + 2] = __half(0.0f);
}

// ---------------------------------------------------------------------------
// Main (measured winner, rounds 4/9/12/13): one block per batch row,
// 256 threads, 4 float4 slots per thread.
//   Phase 1: threads 0..63 -> (float4 table base, frac as half2).
//   Phase 2: per slot: LDG.128 (L1/L2-resident table) -> 2xHFMA2/HMAX2 ->
//            4 CVT -> STG.128 streaming. Interleaved per slot.
// ---------------------------------------------------------------------------
__global__ __launch_bounds__(256, 8)
void pwl_main(const float* __restrict__ X,
              float* __restrict__ out) {
    __shared__ int      s_base[NF];
    __shared__ unsigned s_fr[NF];

    int b = blockIdx.x;
    int t = threadIdx.x;

    if (t < NF) {
        float x = X[b * NF + t];
        int j = 0;
#pragma unroll
        for (int k = 1; k <= NP; k++) j += (x >= g_bT[k * NF + t]) ? 1 : 0;
        float frac = 0.0f;
        if (j < NP) {
            float lo = g_bT[j * NF + t];
            float hi = g_bT[(j + 1) * NF + t];
            frac = fminf(fmaxf((x - lo) / (hi - lo), 0.0f), 1.0f);
        }
        s_base[t] = (t * NB + j) << 4;      // float4 index of P[f][j] chunk 0
        __half2 h2 = __float2half2_rn(frac);
        s_fr[t] = *reinterpret_cast<unsigned*>(&h2);
    }
    __syncthreads();

    float4* out4 = reinterpret_cast<float4*>(out + (size_t)b * (NF * E));
    const __half2 zero2 = __float2half2_rn(0.0f);

#pragma unroll
    for (int rep = 0; rep < 4; rep++) {
        int i  = t + rep * 256;             // 0..1023 float4 slots
        int f  = i >> 4;                    // 16 float4 per feature
        int e4 = i & 15;
        int base     = s_base[f];
        unsigned fru = s_fr[f];
        __half2 f2 = *reinterpret_cast<__half2*>(&fru);

        float4 p = g_P4[base + e4];
        __half2 c01 = *reinterpret_cast<__half2*>(&p.x);
        __half2 w01 = *reinterpret_cast<__half2*>(&p.y);
        __half2 c23 = *reinterpret_cast<__half2*>(&p.z);
        __half2 w23 = *reinterpret_cast<__half2*>(&p.w);

        __half2 r01 = __hmax2(__hfma2(f2, w01, c01), zero2);
        __half2 r23 = __hmax2(__hfma2(f2, w23, c23), zero2);
        float2 o01 = __half22float2(r01);
        float2 o23 = __half22float2(r23);

        __stcs(out4 + i, make_float4(o01.x, o01.y, o23.x, o23.y));
    }
}

extern "C" void kernel_launch(void* const* d_in, const int* in_sizes, int n_in,
                              void* d_out, int out_size) {
    const float* X      = (const float*)d_in[0];   // (32768, 64)
    const float* bounds = (const float*)d_in[1];   // (64, 33)
    const float* W      = (const float*)d_in[2];   // (64, 32, 64)
    const float* bias   = (const float*)d_in[3];   // (64, 64)
    float* out = (float*)d_out;                    // (32768, 4096)

    pwl_prep<<<(NF * E + 255) / 256, 256>>>(W, bias, bounds);
    pwl_main<<<BATCH, 256>>>(X, out);
}